// round 6
// baseline (speedup 1.0000x reference)
#include <cuda_runtime.h>
#include <cuda_bf16.h>

#define DIM     128
#define ROWV    32            // float4 per full row
#define SLICE_V 4             // float4 per D-slice (16 floats)
#define NSLICE  8             // DIM / 16
#define S3_THREADS 512
#define ENT_PER_ITER (S3_THREADS / SLICE_V)   // 128 entities per CTA iteration
#define S3_GRIDX 56           // 56 * 8 slices = 448 CTAs ≈ 3 per SM
#define S3_SMEM_MAX (70 * 1024)

// ---------------------------------------------------------------------------
// Kernel 1 (sub2): one block of 512 threads per type node c.
// ---------------------------------------------------------------------------
__global__ __launch_bounds__(512)
void sub2_kernel(const float* __restrict__ emb,
                 const int*   __restrict__ s2row,
                 const int*   __restrict__ lspec,
                 const int*   __restrict__ rcom,
                 float*       __restrict__ out,
                 float addc, int deg2)
{
    __shared__ float part[4][DIM];

    const int c = blockIdx.x;
    const int d = threadIdx.x & (DIM - 1);
    const int g = threadIdx.x >> 7;

    const int* __restrict__ e = s2row + (size_t)c * deg2;
    const int chunk = deg2 >> 2;
    const int j0 = g * chunk;
    const int j1 = (g == 3) ? deg2 : j0 + chunk;

    float acc = 0.0f;
    #pragma unroll 8
    for (int j = j0; j < j1; ++j) {
        int src = __ldg(&lspec[__ldg(&e[j])]);
        acc += __ldcs(&emb[(size_t)src * DIM + d]);
    }
    part[g][d] = acc;
    __syncthreads();

    if (g == 0) {
        const int tgt = rcom[c];
        float v = __ldg(&emb[(size_t)tgt * DIM + d])
                + part[0][d] + part[1][d] + part[2][d] + part[3][d] + addc;
        out[(size_t)tgt * DIM + d] = v;   // stays L2-hot for sub3 staging
    }
}

// ---------------------------------------------------------------------------
// Kernel 2 (sub3), deg3==4 precomputed-group-sum smem path.
// grid = (S3_GRIDX, NSLICE). Each CTA owns a 16-float D-slice + entity range.
// Staging: S[j] = sum_{k=0..3} out[lcom[(j+k) mod n_typ]]  (slice, 64 KB).
// Hot loop per entity: if the 4 edges are consecutive-mod (the common case),
// ONE LDS.128 of S[e.x] replaces 4 gathers. Generic fallback gathers from
// global (L2-hot) otherwise -> correct for arbitrary edge lists.
// ---------------------------------------------------------------------------
extern __shared__ float4 s_S[];   // [n_typ * SLICE_V]

__global__ __launch_bounds__(S3_THREADS)
void sub3_smem(const float4* __restrict__ emb4,
               const int4*   __restrict__ edges4,
               const int*    __restrict__ lcom,
               const int*    __restrict__ rspec,
               float4*       __restrict__ out4,
               int n_ent, int n_typ, float add, float inv_sum)
{
    const int sbase = blockIdx.y * SLICE_V;          // float4 offset within row
    const int tid   = threadIdx.x;
    const int sub   = tid & (SLICE_V - 1);           // 0..3 chunk within slice
    const int eoff  = tid >> 2;                      // 0..127 entity offset

    // ---- stage group-sum slice: S[j] = sum of 4 consecutive table rows ----
    for (int i = tid; i < n_typ * SLICE_V; i += S3_THREADS) {
        const int j = i >> 2;
        const int c = i & (SLICE_V - 1);
        int j1 = j + 1; if (j1 >= n_typ) j1 -= n_typ;
        int j2 = j + 2; if (j2 >= n_typ) j2 -= n_typ;
        int j3 = j + 3; if (j3 >= n_typ) j3 -= n_typ;
        const int t0 = __ldg(&lcom[j]);
        const int t1 = __ldg(&lcom[j1]);
        const int t2 = __ldg(&lcom[j2]);
        const int t3 = __ldg(&lcom[j3]);
        float4 v0 = __ldg(&out4[(size_t)t0 * ROWV + sbase + c]);
        float4 v1 = __ldg(&out4[(size_t)t1 * ROWV + sbase + c]);
        float4 v2 = __ldg(&out4[(size_t)t2 * ROWV + sbase + c]);
        float4 v3 = __ldg(&out4[(size_t)t3 * ROWV + sbase + c]);
        float4 s;
        s.x = (v0.x + v1.x) + (v2.x + v3.x);
        s.y = (v0.y + v1.y) + (v2.y + v3.y);
        s.z = (v0.z + v1.z) + (v2.z + v3.z);
        s.w = (v0.w + v1.w) + (v2.w + v3.w);
        s_S[i] = s;
    }
    __syncthreads();

    // ---- entity range ----
    const int per = (n_ent + gridDim.x - 1) / gridDim.x;
    const int e0  = blockIdx.x * per;
    const int e1  = min(e0 + per, n_ent);
    const int span = e1 - e0;
    if (span <= 0) return;
    const int full = span / ENT_PER_ITER * ENT_PER_ITER;

    // ---- main streaming loop ----
    int eb = e0;
    #pragma unroll 4
    for (; eb < e0 + full; eb += ENT_PER_ITER) {
        const int ent = eb + eoff;
        const int4 e = __ldg(&edges4[ent]);
        const int r  = __ldg(&rspec[ent]);
        float4 iv = __ldcs(&emb4[(size_t)r * ROWV + sbase + sub]);

        const int d1 = e.y - e.x, d2 = e.z - e.x, d3 = e.w - e.x;
        const bool ok = (d1 == 1 || d1 == 1 - n_typ)
                     && (d2 == 2 || d2 == 2 - n_typ)
                     && (d3 == 3 || d3 == 3 - n_typ);
        float4 a;
        if (ok) {
            a = s_S[e.x * SLICE_V + sub];
        } else {
            const int t0 = __ldg(&lcom[e.x]);
            const int t1 = __ldg(&lcom[e.y]);
            const int t2 = __ldg(&lcom[e.z]);
            const int t3 = __ldg(&lcom[e.w]);
            float4 g0 = __ldg(&out4[(size_t)t0 * ROWV + sbase + sub]);
            float4 g1 = __ldg(&out4[(size_t)t1 * ROWV + sbase + sub]);
            float4 g2 = __ldg(&out4[(size_t)t2 * ROWV + sbase + sub]);
            float4 g3 = __ldg(&out4[(size_t)t3 * ROWV + sbase + sub]);
            a.x = (g0.x + g1.x) + (g2.x + g3.x);
            a.y = (g0.y + g1.y) + (g2.y + g3.y);
            a.z = (g0.z + g1.z) + (g2.z + g3.z);
            a.w = (g0.w + g1.w) + (g2.w + g3.w);
        }
        float4 w;
        w.x = iv.x * (1.0f - (a.x + add) * inv_sum);
        w.y = iv.y * (1.0f - (a.y + add) * inv_sum);
        w.z = iv.z * (1.0f - (a.z + add) * inv_sum);
        w.w = iv.w * (1.0f - (a.w + add) * inv_sum);
        __stcs(&out4[(size_t)r * ROWV + sbase + sub], w);
    }

    // ---- tail ----
    for (; eb < e1; eb += ENT_PER_ITER) {
        const int ent = eb + eoff;
        if (ent < e1) {
            const int4 e = __ldg(&edges4[ent]);
            const int r  = __ldg(&rspec[ent]);
            float4 iv = __ldcs(&emb4[(size_t)r * ROWV + sbase + sub]);
            const int d1 = e.y - e.x, d2 = e.z - e.x, d3 = e.w - e.x;
            const bool ok = (d1 == 1 || d1 == 1 - n_typ)
                         && (d2 == 2 || d2 == 2 - n_typ)
                         && (d3 == 3 || d3 == 3 - n_typ);
            float4 a;
            if (ok) {
                a = s_S[e.x * SLICE_V + sub];
            } else {
                const int t0 = __ldg(&lcom[e.x]);
                const int t1 = __ldg(&lcom[e.y]);
                const int t2 = __ldg(&lcom[e.z]);
                const int t3 = __ldg(&lcom[e.w]);
                float4 g0 = __ldg(&out4[(size_t)t0 * ROWV + sbase + sub]);
                float4 g1 = __ldg(&out4[(size_t)t1 * ROWV + sbase + sub]);
                float4 g2 = __ldg(&out4[(size_t)t2 * ROWV + sbase + sub]);
                float4 g3 = __ldg(&out4[(size_t)t3 * ROWV + sbase + sub]);
                a.x = (g0.x + g1.x) + (g2.x + g3.x);
                a.y = (g0.y + g1.y) + (g2.y + g3.y);
                a.z = (g0.z + g1.z) + (g2.z + g3.z);
                a.w = (g0.w + g1.w) + (g2.w + g3.w);
            }
            float4 w;
            w.x = iv.x * (1.0f - (a.x + add) * inv_sum);
            w.y = iv.y * (1.0f - (a.y + add) * inv_sum);
            w.z = iv.z * (1.0f - (a.z + add) * inv_sum);
            w.w = iv.w * (1.0f - (a.w + add) * inv_sum);
            __stcs(&out4[(size_t)r * ROWV + sbase + sub], w);
        }
    }
}

// ---------------------------------------------------------------------------
// Generic fallback (any deg3 / oversize n_typ): warp per entity.
// ---------------------------------------------------------------------------
__global__ __launch_bounds__(256)
void sub3_kernel_gen(const float* __restrict__ emb,
                     const int*   __restrict__ s3row,
                     const int*   __restrict__ lcom,
                     const int*   __restrict__ rspec,
                     float*       __restrict__ out,
                     int n_ent, float n_typ_f, int deg3)
{
    const int warp = threadIdx.x >> 5;
    const int lane = threadIdx.x & 31;
    const int n = blockIdx.x * (blockDim.x >> 5) + warp;
    if (n >= n_ent) return;

    const float4* __restrict__ out4 = (const float4*)out;
    const int* __restrict__ e = s3row + (size_t)n * deg3;

    float4 acc = make_float4(0.f, 0.f, 0.f, 0.f);
    for (int j = 0; j < deg3; ++j) {
        int t = __ldg(&lcom[__ldg(&e[j])]);
        float4 v = __ldg(&out4[(size_t)t * ROWV + lane]);
        acc.x += v.x; acc.y += v.y; acc.z += v.z; acc.w += v.w;
    }
    const float add     = n_typ_f - (float)deg3;
    const float inv_sum = 1.0f / (1.0f + (float)deg3);
    const int   tgt     = rspec[n];
    float4 iv = __ldcs(&((const float4*)emb)[(size_t)tgt * ROWV + lane]);
    float4 r;
    r.x = iv.x * (1.0f - (acc.x + add) * inv_sum);
    r.y = iv.y * (1.0f - (acc.y + add) * inv_sum);
    r.z = iv.z * (1.0f - (acc.z + add) * inv_sum);
    r.w = iv.w * (1.0f - (acc.w + add) * inv_sum);
    __stcs(&((float4*)out)[(size_t)tgt * ROWV + lane], r);
}

// ---------------------------------------------------------------------------
// Launch. Inputs (metadata order):
//  0 all_node_embedding f32 | 1 sub2_row | 2 sub2_col | 3 sub3_row | 4 sub3_col
//  5 left_specific | 6 right_common | 7 left_common | 8 right_specific
// ---------------------------------------------------------------------------
extern "C" void kernel_launch(void* const* d_in, const int* in_sizes, int n_in,
                              void* d_out, int out_size)
{
    const float* emb   = (const float*)d_in[0];
    const int*   s2row = (const int*)  d_in[1];
    const int*   s3row = (const int*)  d_in[3];
    const int*   lspec = (const int*)  d_in[5];
    const int*   rcom  = (const int*)  d_in[6];
    const int*   lcom  = (const int*)  d_in[7];
    const int*   rspec = (const int*)  d_in[8];
    float*       out   = (float*)d_out;

    const int n_ent = in_sizes[5];
    const int n_typ = in_sizes[6];
    const int deg2  = in_sizes[1] / n_typ;
    const int deg3  = in_sizes[3] / in_sizes[8];

    // ---- sub2 ----
    sub2_kernel<<<n_typ, 512>>>(emb, s2row, lspec, rcom, out,
                                (float)n_ent - (float)deg2, deg2);

    // ---- sub3 ----
    const size_t smem_bytes = (size_t)n_typ * SLICE_V * sizeof(float4); // n_typ*64B
    if (deg3 == 4 && smem_bytes <= S3_SMEM_MAX) {
        static int attr_set = 0;
        if (!attr_set) {
            cudaFuncSetAttribute(sub3_smem,
                                 cudaFuncAttributeMaxDynamicSharedMemorySize,
                                 S3_SMEM_MAX);
            attr_set = 1;
        }
        dim3 grid(S3_GRIDX, NSLICE);
        sub3_smem<<<grid, S3_THREADS, smem_bytes>>>(
            (const float4*)emb, (const int4*)s3row, lcom, rspec,
            (float4*)out, n_ent, n_typ,
            (float)n_typ - 4.0f, 1.0f / 5.0f);
    } else {
        const int warps_per_block = 8;
        const int blocks = (n_ent + warps_per_block - 1) / warps_per_block;
        sub3_kernel_gen<<<blocks, warps_per_block * 32>>>(
            emb, s3row, lcom, rspec, out, n_ent, (float)n_typ, deg3);
    }
}

// round 7
// speedup vs baseline: 1.6650x; 1.6650x over previous
#include <cuda_runtime.h>
#include <cuda_bf16.h>

#define DIM   128
#define ROWV  32              // float4 per row
#define NTYP_MAX 4096

// Precomputed group-sum table: S[j] = sum_{k=0..3} out[lcom[(j+k)%n_typ]]
// 4096 rows x 512 B = 2 MB static scratch (L2-resident for n_typ=1000).
__device__ float4 g_S[NTYP_MAX * ROWV];

// ---------------------------------------------------------------------------
// Kernel 1 (sub2): one block of 512 threads per type node c.
// ---------------------------------------------------------------------------
__global__ __launch_bounds__(512)
void sub2_kernel(const float* __restrict__ emb,
                 const int*   __restrict__ s2row,
                 const int*   __restrict__ lspec,
                 const int*   __restrict__ rcom,
                 float*       __restrict__ out,
                 float addc, int deg2)
{
    __shared__ float part[4][DIM];

    const int c = blockIdx.x;
    const int d = threadIdx.x & (DIM - 1);
    const int g = threadIdx.x >> 7;

    const int* __restrict__ e = s2row + (size_t)c * deg2;
    const int chunk = deg2 >> 2;
    const int j0 = g * chunk;
    const int j1 = (g == 3) ? deg2 : j0 + chunk;

    float acc = 0.0f;
    #pragma unroll 8
    for (int j = j0; j < j1; ++j) {
        int src = __ldg(&lspec[__ldg(&e[j])]);
        acc += __ldcs(&emb[(size_t)src * DIM + d]);
    }
    part[g][d] = acc;
    __syncthreads();

    if (g == 0) {
        const int tgt = rcom[c];
        float v = __ldg(&emb[(size_t)tgt * DIM + d])
                + part[0][d] + part[1][d] + part[2][d] + part[3][d] + addc;
        out[(size_t)tgt * DIM + d] = v;   // stays L2-hot for S build + gathers
    }
}

// ---------------------------------------------------------------------------
// Kernel 2: build S[j] = sum of 4 consecutive (mod n_typ) updated type rows.
// grid = n_typ blocks x 128 threads (1 thread per float of the row).
// ---------------------------------------------------------------------------
__global__ __launch_bounds__(128)
void build_S_kernel(const float4* __restrict__ out4,
                    const int*    __restrict__ lcom,
                    int n_typ)
{
    const int j = blockIdx.x;
    const int q = threadIdx.x >> 2;           // 0..31 float4 index
    const int comp = threadIdx.x & 3;         // unused split; use q only
    if (comp) { /* 4 threads per float4 is wasteful; remap below */ }

    // remap: 128 threads -> 32 float4 lanes, 4 j-neighbors handled per thread
    // simpler: thread t handles float4 lane (t & 31), neighbor (t >> 5)
    const int lane = threadIdx.x & 31;
    const int k    = threadIdx.x >> 5;        // 0..3
    int jj = j + k; if (jj >= n_typ) jj -= n_typ;
    const int t = __ldg(&lcom[jj]);
    float4 v = __ldg(&out4[(size_t)t * ROWV + lane]);

    __shared__ float4 red[4][ROWV];
    red[k][lane] = v;
    __syncthreads();
    if (k == 0) {
        float4 a = red[0][lane], b = red[1][lane],
               c = red[2][lane], d = red[3][lane];
        float4 s;
        s.x = (a.x + b.x) + (c.x + d.x);
        s.y = (a.y + b.y) + (c.y + d.y);
        s.z = (a.z + b.z) + (c.z + d.z);
        s.w = (a.w + b.w) + (c.w + d.w);
        g_S[(size_t)j * ROWV + lane] = s;
    }
}

// ---------------------------------------------------------------------------
// Kernel 3 (sub3), deg3==4: one warp per TWO entity rows, lane owns one
// float4 of the 512B row. Edge vector is WARP-UNIFORM (broadcast load), so
// the consecutive-pattern check is a uniform branch: fast path does ONE L2
// gather of S[e.x]; fallback does 4 gathers (correct for arbitrary edges).
// Entity stream read/write uses streaming hints to protect L2 for S.
// ---------------------------------------------------------------------------
__global__ __launch_bounds__(256)
void sub3_kernel(const float4* __restrict__ emb4,
                 const int4*   __restrict__ edges4,
                 const int*    __restrict__ lcom,
                 const int*    __restrict__ rspec,
                 float4*       __restrict__ out4,
                 int n_ent, int n_typ, float add, float inv_sum)
{
    const int warp = threadIdx.x >> 5;
    const int lane = threadIdx.x & 31;
    const int base = (blockIdx.x * (blockDim.x >> 5) + warp) * 2;
    if (base >= n_ent) return;
    const bool has1 = (base + 1) < n_ent;

    const int4 e0 = __ldg(&edges4[base]);
    const int4 e1 = has1 ? __ldg(&edges4[base + 1]) : e0;
    const int  r0 = __ldg(&rspec[base]);
    const int  r1 = has1 ? __ldg(&rspec[base + 1]) : r0;

    float4 iv0 = __ldcs(&emb4[(size_t)r0 * ROWV + lane]);
    float4 iv1 = __ldcs(&emb4[(size_t)r1 * ROWV + lane]);

    // warp-uniform pattern checks
    const int d01 = e0.y - e0.x, d02 = e0.z - e0.x, d03 = e0.w - e0.x;
    const bool ok0 = (d01 == 1 || d01 == 1 - n_typ)
                  && (d02 == 2 || d02 == 2 - n_typ)
                  && (d03 == 3 || d03 == 3 - n_typ);
    const int d11 = e1.y - e1.x, d12 = e1.z - e1.x, d13 = e1.w - e1.x;
    const bool ok1 = (d11 == 1 || d11 == 1 - n_typ)
                  && (d12 == 2 || d12 == 2 - n_typ)
                  && (d13 == 3 || d13 == 3 - n_typ);

    float4 a0, a1;
    if (ok0) {
        a0 = __ldg(&g_S[(size_t)e0.x * ROWV + lane]);
    } else {
        const int t0 = __ldg(&lcom[e0.x]), t1 = __ldg(&lcom[e0.y]);
        const int t2 = __ldg(&lcom[e0.z]), t3 = __ldg(&lcom[e0.w]);
        float4 g0 = __ldg(&out4[(size_t)t0 * ROWV + lane]);
        float4 g1 = __ldg(&out4[(size_t)t1 * ROWV + lane]);
        float4 g2 = __ldg(&out4[(size_t)t2 * ROWV + lane]);
        float4 g3 = __ldg(&out4[(size_t)t3 * ROWV + lane]);
        a0.x = (g0.x + g1.x) + (g2.x + g3.x);
        a0.y = (g0.y + g1.y) + (g2.y + g3.y);
        a0.z = (g0.z + g1.z) + (g2.z + g3.z);
        a0.w = (g0.w + g1.w) + (g2.w + g3.w);
    }
    if (ok1) {
        a1 = __ldg(&g_S[(size_t)e1.x * ROWV + lane]);
    } else {
        const int t0 = __ldg(&lcom[e1.x]), t1 = __ldg(&lcom[e1.y]);
        const int t2 = __ldg(&lcom[e1.z]), t3 = __ldg(&lcom[e1.w]);
        float4 g0 = __ldg(&out4[(size_t)t0 * ROWV + lane]);
        float4 g1 = __ldg(&out4[(size_t)t1 * ROWV + lane]);
        float4 g2 = __ldg(&out4[(size_t)t2 * ROWV + lane]);
        float4 g3 = __ldg(&out4[(size_t)t3 * ROWV + lane]);
        a1.x = (g0.x + g1.x) + (g2.x + g3.x);
        a1.y = (g0.y + g1.y) + (g2.y + g3.y);
        a1.z = (g0.z + g1.z) + (g2.z + g3.z);
        a1.w = (g0.w + g1.w) + (g2.w + g3.w);
    }

    float4 w0;
    w0.x = iv0.x * (1.0f - (a0.x + add) * inv_sum);
    w0.y = iv0.y * (1.0f - (a0.y + add) * inv_sum);
    w0.z = iv0.z * (1.0f - (a0.z + add) * inv_sum);
    w0.w = iv0.w * (1.0f - (a0.w + add) * inv_sum);
    __stcs(&out4[(size_t)r0 * ROWV + lane], w0);

    if (has1) {
        float4 w1;
        w1.x = iv1.x * (1.0f - (a1.x + add) * inv_sum);
        w1.y = iv1.y * (1.0f - (a1.y + add) * inv_sum);
        w1.z = iv1.z * (1.0f - (a1.z + add) * inv_sum);
        w1.w = iv1.w * (1.0f - (a1.w + add) * inv_sum);
        __stcs(&out4[(size_t)r1 * ROWV + lane], w1);
    }
}

// ---------------------------------------------------------------------------
// Generic fallback (deg3 != 4 or n_typ > NTYP_MAX): warp per entity.
// ---------------------------------------------------------------------------
__global__ __launch_bounds__(256)
void sub3_kernel_gen(const float* __restrict__ emb,
                     const int*   __restrict__ s3row,
                     const int*   __restrict__ lcom,
                     const int*   __restrict__ rspec,
                     float*       __restrict__ out,
                     int n_ent, float n_typ_f, int deg3)
{
    const int warp = threadIdx.x >> 5;
    const int lane = threadIdx.x & 31;
    const int n = blockIdx.x * (blockDim.x >> 5) + warp;
    if (n >= n_ent) return;

    const float4* __restrict__ out4 = (const float4*)out;
    const int* __restrict__ e = s3row + (size_t)n * deg3;

    float4 acc = make_float4(0.f, 0.f, 0.f, 0.f);
    for (int j = 0; j < deg3; ++j) {
        int t = __ldg(&lcom[__ldg(&e[j])]);
        float4 v = __ldg(&out4[(size_t)t * ROWV + lane]);
        acc.x += v.x; acc.y += v.y; acc.z += v.z; acc.w += v.w;
    }
    const float add     = n_typ_f - (float)deg3;
    const float inv_sum = 1.0f / (1.0f + (float)deg3);
    const int   tgt     = rspec[n];
    float4 iv = __ldcs(&((const float4*)emb)[(size_t)tgt * ROWV + lane]);
    float4 r;
    r.x = iv.x * (1.0f - (acc.x + add) * inv_sum);
    r.y = iv.y * (1.0f - (acc.y + add) * inv_sum);
    r.z = iv.z * (1.0f - (acc.z + add) * inv_sum);
    r.w = iv.w * (1.0f - (acc.w + add) * inv_sum);
    __stcs(&((float4*)out)[(size_t)tgt * ROWV + lane], r);
}

// ---------------------------------------------------------------------------
// Launch. Inputs (metadata order):
//  0 all_node_embedding f32 | 1 sub2_row | 2 sub2_col | 3 sub3_row | 4 sub3_col
//  5 left_specific | 6 right_common | 7 left_common | 8 right_specific
// ---------------------------------------------------------------------------
extern "C" void kernel_launch(void* const* d_in, const int* in_sizes, int n_in,
                              void* d_out, int out_size)
{
    const float* emb   = (const float*)d_in[0];
    const int*   s2row = (const int*)  d_in[1];
    const int*   s3row = (const int*)  d_in[3];
    const int*   lspec = (const int*)  d_in[5];
    const int*   rcom  = (const int*)  d_in[6];
    const int*   lcom  = (const int*)  d_in[7];
    const int*   rspec = (const int*)  d_in[8];
    float*       out   = (float*)d_out;

    const int n_ent = in_sizes[5];
    const int n_typ = in_sizes[6];
    const int deg2  = in_sizes[1] / n_typ;
    const int deg3  = in_sizes[3] / in_sizes[8];

    // ---- sub2: update type rows of out ----
    sub2_kernel<<<n_typ, 512>>>(emb, s2row, lspec, rcom, out,
                                (float)n_ent - (float)deg2, deg2);

    if (deg3 == 4 && n_typ <= NTYP_MAX) {
        // ---- build group-sum table S (L2-resident) ----
        build_S_kernel<<<n_typ, 128>>>((const float4*)out, lcom, n_typ);

        // ---- sub3 streaming update ----
        const int warps_per_block = 8;
        const int ents_per_block  = warps_per_block * 2;
        const int blocks = (n_ent + ents_per_block - 1) / ents_per_block;
        sub3_kernel<<<blocks, warps_per_block * 32>>>(
            (const float4*)emb, (const int4*)s3row, lcom, rspec,
            (float4*)out, n_ent, n_typ,
            (float)n_typ - 4.0f, 1.0f / 5.0f);
    } else {
        const int warps_per_block = 8;
        const int blocks = (n_ent + warps_per_block - 1) / warps_per_block;
        sub3_kernel_gen<<<blocks, warps_per_block * 32>>>(
            emb, s3row, lcom, rspec, out, n_ent, (float)n_typ, deg3);
    }
}

// round 8
// speedup vs baseline: 1.7332x; 1.0409x over previous
#include <cuda_runtime.h>
#include <cuda_bf16.h>

#define DIM   128
#define ROWV  32              // float4 per row
#define NTYP_MAX 4096

// Precomputed group-sum table: S[j] = sum_{k=0..3} out[lcom[(j+k)%n_typ]]
// L2-resident for n_typ=1000 (512 KB live).
__device__ float4 g_S[NTYP_MAX * ROWV];

// ---------------------------------------------------------------------------
// Kernel 1 (sub2) fast path (deg2 == 64): one block of 512 threads per type.
// 16 groups x 32 lanes. Group g loads its 4 edge indices as ONE int4, then
// 4 parallel lspec lookups, then 4 independent float4 streaming loads
// (64B in flight per thread). Two-stage smem reduction, float4 throughout.
// ---------------------------------------------------------------------------
__global__ __launch_bounds__(512)
void sub2_kernel_d64(const float4* __restrict__ emb4,
                     const int4*   __restrict__ s2row4,  // s2row as int4
                     const int*    __restrict__ lspec,
                     const int*    __restrict__ rcom,
                     float4*       __restrict__ out4,
                     float addc)
{
    __shared__ float4 part[16][ROWV];

    const int c    = blockIdx.x;
    const int lane = threadIdx.x & 31;   // float4 lane within row
    const int g    = threadIdx.x >> 5;   // 0..15 edge group

    // 4 edge indices for this group in one 16B load
    const int4 ei = __ldg(&s2row4[c * 16 + g]);
    const int s0 = __ldg(&lspec[ei.x]);
    const int s1 = __ldg(&lspec[ei.y]);
    const int s2 = __ldg(&lspec[ei.z]);
    const int s3 = __ldg(&lspec[ei.w]);

    float4 v0 = __ldcs(&emb4[(size_t)s0 * ROWV + lane]);
    float4 v1 = __ldcs(&emb4[(size_t)s1 * ROWV + lane]);
    float4 v2 = __ldcs(&emb4[(size_t)s2 * ROWV + lane]);
    float4 v3 = __ldcs(&emb4[(size_t)s3 * ROWV + lane]);

    float4 a;
    a.x = (v0.x + v1.x) + (v2.x + v3.x);
    a.y = (v0.y + v1.y) + (v2.y + v3.y);
    a.z = (v0.z + v1.z) + (v2.z + v3.z);
    a.w = (v0.w + v1.w) + (v2.w + v3.w);
    part[g][lane] = a;
    __syncthreads();

    // stage 1: groups 0..3 fold 4 partials each
    if (g < 4) {
        float4 p0 = part[g][lane];
        float4 p1 = part[g + 4][lane];
        float4 p2 = part[g + 8][lane];
        float4 p3 = part[g + 12][lane];
        float4 s;
        s.x = (p0.x + p1.x) + (p2.x + p3.x);
        s.y = (p0.y + p1.y) + (p2.y + p3.y);
        s.z = (p0.z + p1.z) + (p2.z + p3.z);
        s.w = (p0.w + p1.w) + (p2.w + p3.w);
        part[g][lane] = s;
    }
    __syncthreads();

    // stage 2: group 0 finishes and writes
    if (g == 0) {
        const int tgt = rcom[c];
        float4 p0 = part[0][lane], p1 = part[1][lane];
        float4 p2 = part[2][lane], p3 = part[3][lane];
        float4 base = __ldg(&emb4[(size_t)tgt * ROWV + lane]);
        float4 r;
        r.x = base.x + (p0.x + p1.x) + (p2.x + p3.x) + addc;
        r.y = base.y + (p0.y + p1.y) + (p2.y + p3.y) + addc;
        r.z = base.z + (p0.z + p1.z) + (p2.z + p3.z) + addc;
        r.w = base.w + (p0.w + p1.w) + (p2.w + p3.w) + addc;
        out4[(size_t)tgt * ROWV + lane] = r;   // default: stays L2-hot
    }
}

// ---------------------------------------------------------------------------
// Kernel 1 generic fallback (any deg2).
// ---------------------------------------------------------------------------
__global__ __launch_bounds__(512)
void sub2_kernel_gen(const float* __restrict__ emb,
                     const int*   __restrict__ s2row,
                     const int*   __restrict__ lspec,
                     const int*   __restrict__ rcom,
                     float*       __restrict__ out,
                     float addc, int deg2)
{
    __shared__ float part[4][DIM];
    const int c = blockIdx.x;
    const int d = threadIdx.x & (DIM - 1);
    const int g = threadIdx.x >> 7;
    const int* __restrict__ e = s2row + (size_t)c * deg2;
    const int chunk = deg2 >> 2;
    const int j0 = g * chunk;
    const int j1 = (g == 3) ? deg2 : j0 + chunk;
    float acc = 0.0f;
    #pragma unroll 8
    for (int j = j0; j < j1; ++j) {
        int src = __ldg(&lspec[__ldg(&e[j])]);
        acc += __ldcs(&emb[(size_t)src * DIM + d]);
    }
    part[g][d] = acc;
    __syncthreads();
    if (g == 0) {
        const int tgt = rcom[c];
        float v = __ldg(&emb[(size_t)tgt * DIM + d])
                + part[0][d] + part[1][d] + part[2][d] + part[3][d] + addc;
        out[(size_t)tgt * DIM + d] = v;
    }
}

// ---------------------------------------------------------------------------
// Kernel 2: build S, flat layout — one thread per float4 of S.
// All reads are L2-hot (type rows just written by sub2). No smem, no syncs.
// ---------------------------------------------------------------------------
__global__ __launch_bounds__(256)
void build_S_kernel(const float4* __restrict__ out4,
                    const int*    __restrict__ lcom,
                    int n_typ)
{
    const int i = blockIdx.x * blockDim.x + threadIdx.x;
    if (i >= n_typ * ROWV) return;
    const int j    = i >> 5;
    const int lane = i & 31;
    int j1 = j + 1; if (j1 >= n_typ) j1 -= n_typ;
    int j2 = j + 2; if (j2 >= n_typ) j2 -= n_typ;
    int j3 = j + 3; if (j3 >= n_typ) j3 -= n_typ;
    const int t0 = __ldg(&lcom[j]);
    const int t1 = __ldg(&lcom[j1]);
    const int t2 = __ldg(&lcom[j2]);
    const int t3 = __ldg(&lcom[j3]);
    float4 v0 = __ldg(&out4[(size_t)t0 * ROWV + lane]);
    float4 v1 = __ldg(&out4[(size_t)t1 * ROWV + lane]);
    float4 v2 = __ldg(&out4[(size_t)t2 * ROWV + lane]);
    float4 v3 = __ldg(&out4[(size_t)t3 * ROWV + lane]);
    float4 s;
    s.x = (v0.x + v1.x) + (v2.x + v3.x);
    s.y = (v0.y + v1.y) + (v2.y + v3.y);
    s.z = (v0.z + v1.z) + (v2.z + v3.z);
    s.w = (v0.w + v1.w) + (v2.w + v3.w);
    g_S[i] = s;
}

// ---------------------------------------------------------------------------
// Kernel 3 (sub3), deg3==4: one warp per TWO entity rows, warp-uniform
// consecutive-pattern check -> ONE L2 gather of S[e.x] per entity (fast
// path); generic 4-gather fallback for arbitrary edges. Streaming hints on
// the entity read/write protect L2 residency of S.
// ---------------------------------------------------------------------------
__global__ __launch_bounds__(256)
void sub3_kernel(const float4* __restrict__ emb4,
                 const int4*   __restrict__ edges4,
                 const int*    __restrict__ lcom,
                 const int*    __restrict__ rspec,
                 float4*       __restrict__ out4,
                 int n_ent, int n_typ, float add, float inv_sum)
{
    const int warp = threadIdx.x >> 5;
    const int lane = threadIdx.x & 31;
    const int base = (blockIdx.x * (blockDim.x >> 5) + warp) * 2;
    if (base >= n_ent) return;
    const bool has1 = (base + 1) < n_ent;

    const int4 e0 = __ldg(&edges4[base]);
    const int4 e1 = has1 ? __ldg(&edges4[base + 1]) : e0;
    const int  r0 = __ldg(&rspec[base]);
    const int  r1 = has1 ? __ldg(&rspec[base + 1]) : r0;

    float4 iv0 = __ldcs(&emb4[(size_t)r0 * ROWV + lane]);
    float4 iv1 = __ldcs(&emb4[(size_t)r1 * ROWV + lane]);

    const int d01 = e0.y - e0.x, d02 = e0.z - e0.x, d03 = e0.w - e0.x;
    const bool ok0 = (d01 == 1 || d01 == 1 - n_typ)
                  && (d02 == 2 || d02 == 2 - n_typ)
                  && (d03 == 3 || d03 == 3 - n_typ);
    const int d11 = e1.y - e1.x, d12 = e1.z - e1.x, d13 = e1.w - e1.x;
    const bool ok1 = (d11 == 1 || d11 == 1 - n_typ)
                  && (d12 == 2 || d12 == 2 - n_typ)
                  && (d13 == 3 || d13 == 3 - n_typ);

    float4 a0, a1;
    if (ok0) {
        a0 = __ldg(&g_S[(size_t)e0.x * ROWV + lane]);
    } else {
        const int t0 = __ldg(&lcom[e0.x]), t1 = __ldg(&lcom[e0.y]);
        const int t2 = __ldg(&lcom[e0.z]), t3 = __ldg(&lcom[e0.w]);
        float4 g0 = __ldg(&out4[(size_t)t0 * ROWV + lane]);
        float4 g1 = __ldg(&out4[(size_t)t1 * ROWV + lane]);
        float4 g2 = __ldg(&out4[(size_t)t2 * ROWV + lane]);
        float4 g3 = __ldg(&out4[(size_t)t3 * ROWV + lane]);
        a0.x = (g0.x + g1.x) + (g2.x + g3.x);
        a0.y = (g0.y + g1.y) + (g2.y + g3.y);
        a0.z = (g0.z + g1.z) + (g2.z + g3.z);
        a0.w = (g0.w + g1.w) + (g2.w + g3.w);
    }
    if (ok1) {
        a1 = __ldg(&g_S[(size_t)e1.x * ROWV + lane]);
    } else {
        const int t0 = __ldg(&lcom[e1.x]), t1 = __ldg(&lcom[e1.y]);
        const int t2 = __ldg(&lcom[e1.z]), t3 = __ldg(&lcom[e1.w]);
        float4 g0 = __ldg(&out4[(size_t)t0 * ROWV + lane]);
        float4 g1 = __ldg(&out4[(size_t)t1 * ROWV + lane]);
        float4 g2 = __ldg(&out4[(size_t)t2 * ROWV + lane]);
        float4 g3 = __ldg(&out4[(size_t)t3 * ROWV + lane]);
        a1.x = (g0.x + g1.x) + (g2.x + g3.x);
        a1.y = (g0.y + g1.y) + (g2.y + g3.y);
        a1.z = (g0.z + g1.z) + (g2.z + g3.z);
        a1.w = (g0.w + g1.w) + (g2.w + g3.w);
    }

    float4 w0;
    w0.x = iv0.x * (1.0f - (a0.x + add) * inv_sum);
    w0.y = iv0.y * (1.0f - (a0.y + add) * inv_sum);
    w0.z = iv0.z * (1.0f - (a0.z + add) * inv_sum);
    w0.w = iv0.w * (1.0f - (a0.w + add) * inv_sum);
    __stcs(&out4[(size_t)r0 * ROWV + lane], w0);

    if (has1) {
        float4 w1;
        w1.x = iv1.x * (1.0f - (a1.x + add) * inv_sum);
        w1.y = iv1.y * (1.0f - (a1.y + add) * inv_sum);
        w1.z = iv1.z * (1.0f - (a1.z + add) * inv_sum);
        w1.w = iv1.w * (1.0f - (a1.w + add) * inv_sum);
        __stcs(&out4[(size_t)r1 * ROWV + lane], w1);
    }
}

// ---------------------------------------------------------------------------
// Generic sub3 fallback (deg3 != 4 or n_typ > NTYP_MAX).
// ---------------------------------------------------------------------------
__global__ __launch_bounds__(256)
void sub3_kernel_gen(const float* __restrict__ emb,
                     const int*   __restrict__ s3row,
                     const int*   __restrict__ lcom,
                     const int*   __restrict__ rspec,
                     float*       __restrict__ out,
                     int n_ent, float n_typ_f, int deg3)
{
    const int warp = threadIdx.x >> 5;
    const int lane = threadIdx.x & 31;
    const int n = blockIdx.x * (blockDim.x >> 5) + warp;
    if (n >= n_ent) return;

    const float4* __restrict__ out4 = (const float4*)out;
    const int* __restrict__ e = s3row + (size_t)n * deg3;

    float4 acc = make_float4(0.f, 0.f, 0.f, 0.f);
    for (int j = 0; j < deg3; ++j) {
        int t = __ldg(&lcom[__ldg(&e[j])]);
        float4 v = __ldg(&out4[(size_t)t * ROWV + lane]);
        acc.x += v.x; acc.y += v.y; acc.z += v.z; acc.w += v.w;
    }
    const float add     = n_typ_f - (float)deg3;
    const float inv_sum = 1.0f / (1.0f + (float)deg3);
    const int   tgt     = rspec[n];
    float4 iv = __ldcs(&((const float4*)emb)[(size_t)tgt * ROWV + lane]);
    float4 r;
    r.x = iv.x * (1.0f - (acc.x + add) * inv_sum);
    r.y = iv.y * (1.0f - (acc.y + add) * inv_sum);
    r.z = iv.z * (1.0f - (acc.z + add) * inv_sum);
    r.w = iv.w * (1.0f - (acc.w + add) * inv_sum);
    __stcs(&((float4*)out)[(size_t)tgt * ROWV + lane], r);
}

// ---------------------------------------------------------------------------
// Launch. Inputs (metadata order):
//  0 all_node_embedding f32 | 1 sub2_row | 2 sub2_col | 3 sub3_row | 4 sub3_col
//  5 left_specific | 6 right_common | 7 left_common | 8 right_specific
// ---------------------------------------------------------------------------
extern "C" void kernel_launch(void* const* d_in, const int* in_sizes, int n_in,
                              void* d_out, int out_size)
{
    const float* emb   = (const float*)d_in[0];
    const int*   s2row = (const int*)  d_in[1];
    const int*   s3row = (const int*)  d_in[3];
    const int*   lspec = (const int*)  d_in[5];
    const int*   rcom  = (const int*)  d_in[6];
    const int*   lcom  = (const int*)  d_in[7];
    const int*   rspec = (const int*)  d_in[8];
    float*       out   = (float*)d_out;

    const int n_ent = in_sizes[5];
    const int n_typ = in_sizes[6];
    const int deg2  = in_sizes[1] / n_typ;
    const int deg3  = in_sizes[3] / in_sizes[8];

    // ---- sub2: update type rows of out ----
    if (deg2 == 64) {
        sub2_kernel_d64<<<n_typ, 512>>>((const float4*)emb, (const int4*)s2row,
                                        lspec, rcom, (float4*)out,
                                        (float)n_ent - (float)deg2);
    } else {
        sub2_kernel_gen<<<n_typ, 512>>>(emb, s2row, lspec, rcom, out,
                                        (float)n_ent - (float)deg2, deg2);
    }

    if (deg3 == 4 && n_typ <= NTYP_MAX) {
        // ---- build group-sum table S (flat, no syncs) ----
        const int s_threads = 256;
        const int s_blocks  = (n_typ * ROWV + s_threads - 1) / s_threads;
        build_S_kernel<<<s_blocks, s_threads>>>((const float4*)out, lcom, n_typ);

        // ---- sub3 streaming update ----
        const int warps_per_block = 8;
        const int ents_per_block  = warps_per_block * 2;
        const int blocks = (n_ent + ents_per_block - 1) / ents_per_block;
        sub3_kernel<<<blocks, warps_per_block * 32>>>(
            (const float4*)emb, (const int4*)s3row, lcom, rspec,
            (float4*)out, n_ent, n_typ,
            (float)n_typ - 4.0f, 1.0f / 5.0f);
    } else {
        const int warps_per_block = 8;
        const int blocks = (n_ent + warps_per_block - 1) / warps_per_block;
        sub3_kernel_gen<<<blocks, warps_per_block * 32>>>(
            emb, s3row, lcom, rspec, out, n_ent, (float)n_typ, deg3);
    }
}

// round 9
// speedup vs baseline: 1.7434x; 1.0059x over previous
#include <cuda_runtime.h>
#include <cuda_bf16.h>

#define DIM   128
#define ROWV  32              // float4 per row
#define NTYP_MAX 4096

// Precomputed group-sum table: S[j] = sum_{k=0..3} out[lcom[(j+k)%n_typ]]
// L2-resident for n_typ=1000 (512 KB live).
__device__ float4 g_S[NTYP_MAX * ROWV];

// ---------------------------------------------------------------------------
// Kernel 1 (sub2) fast path (deg2 == 64): one block of 256 threads per type.
// 8 groups x 32 lanes. Group g owns 8 edges: 2 independent int4 index loads,
// 8 independent lspec lookups, 8 independent float4 streaming row loads
// (128B in flight per thread). Register 8-way sum + one smem reduce stage.
// ---------------------------------------------------------------------------
__global__ __launch_bounds__(256)
void sub2_kernel_d64(const float4* __restrict__ emb4,
                     const int4*   __restrict__ s2row4,  // s2row as int4
                     const int*    __restrict__ lspec,
                     const int*    __restrict__ rcom,
                     float4*       __restrict__ out4,
                     float addc)
{
    __shared__ float4 part[8][ROWV];

    const int c    = blockIdx.x;
    const int lane = threadIdx.x & 31;   // float4 lane within row
    const int g    = threadIdx.x >> 5;   // 0..7 edge group (8 edges each)

    // 8 edge indices for this group in two 16B loads (independent)
    const int4 ea = __ldg(&s2row4[c * 16 + g * 2]);
    const int4 eb = __ldg(&s2row4[c * 16 + g * 2 + 1]);

    // 8 independent lspec lookups
    const int s0 = __ldg(&lspec[ea.x]);
    const int s1 = __ldg(&lspec[ea.y]);
    const int s2 = __ldg(&lspec[ea.z]);
    const int s3 = __ldg(&lspec[ea.w]);
    const int s4 = __ldg(&lspec[eb.x]);
    const int s5 = __ldg(&lspec[eb.y]);
    const int s6 = __ldg(&lspec[eb.z]);
    const int s7 = __ldg(&lspec[eb.w]);

    // 8 independent streaming row loads (read-once)
    float4 v0 = __ldcs(&emb4[(size_t)s0 * ROWV + lane]);
    float4 v1 = __ldcs(&emb4[(size_t)s1 * ROWV + lane]);
    float4 v2 = __ldcs(&emb4[(size_t)s2 * ROWV + lane]);
    float4 v3 = __ldcs(&emb4[(size_t)s3 * ROWV + lane]);
    float4 v4 = __ldcs(&emb4[(size_t)s4 * ROWV + lane]);
    float4 v5 = __ldcs(&emb4[(size_t)s5 * ROWV + lane]);
    float4 v6 = __ldcs(&emb4[(size_t)s6 * ROWV + lane]);
    float4 v7 = __ldcs(&emb4[(size_t)s7 * ROWV + lane]);

    float4 a;
    a.x = ((v0.x + v1.x) + (v2.x + v3.x)) + ((v4.x + v5.x) + (v6.x + v7.x));
    a.y = ((v0.y + v1.y) + (v2.y + v3.y)) + ((v4.y + v5.y) + (v6.y + v7.y));
    a.z = ((v0.z + v1.z) + (v2.z + v3.z)) + ((v4.z + v5.z) + (v6.z + v7.z));
    a.w = ((v0.w + v1.w) + (v2.w + v3.w)) + ((v4.w + v5.w) + (v6.w + v7.w));
    part[g][lane] = a;
    __syncthreads();

    if (g == 0) {
        const int tgt = rcom[c];
        float4 p0 = part[0][lane], p1 = part[1][lane];
        float4 p2 = part[2][lane], p3 = part[3][lane];
        float4 p4 = part[4][lane], p5 = part[5][lane];
        float4 p6 = part[6][lane], p7 = part[7][lane];
        float4 base = __ldg(&emb4[(size_t)tgt * ROWV + lane]);
        float4 r;
        r.x = base.x + ((p0.x + p1.x) + (p2.x + p3.x))
                     + ((p4.x + p5.x) + (p6.x + p7.x)) + addc;
        r.y = base.y + ((p0.y + p1.y) + (p2.y + p3.y))
                     + ((p4.y + p5.y) + (p6.y + p7.y)) + addc;
        r.z = base.z + ((p0.z + p1.z) + (p2.z + p3.z))
                     + ((p4.z + p5.z) + (p6.z + p7.z)) + addc;
        r.w = base.w + ((p0.w + p1.w) + (p2.w + p3.w))
                     + ((p4.w + p5.w) + (p6.w + p7.w)) + addc;
        out4[(size_t)tgt * ROWV + lane] = r;   // default: stays L2-hot
    }
}

// ---------------------------------------------------------------------------
// Kernel 1 generic fallback (any deg2).
// ---------------------------------------------------------------------------
__global__ __launch_bounds__(512)
void sub2_kernel_gen(const float* __restrict__ emb,
                     const int*   __restrict__ s2row,
                     const int*   __restrict__ lspec,
                     const int*   __restrict__ rcom,
                     float*       __restrict__ out,
                     float addc, int deg2)
{
    __shared__ float part[4][DIM];
    const int c = blockIdx.x;
    const int d = threadIdx.x & (DIM - 1);
    const int g = threadIdx.x >> 7;
    const int* __restrict__ e = s2row + (size_t)c * deg2;
    const int chunk = deg2 >> 2;
    const int j0 = g * chunk;
    const int j1 = (g == 3) ? deg2 : j0 + chunk;
    float acc = 0.0f;
    #pragma unroll 8
    for (int j = j0; j < j1; ++j) {
        int src = __ldg(&lspec[__ldg(&e[j])]);
        acc += __ldcs(&emb[(size_t)src * DIM + d]);
    }
    part[g][d] = acc;
    __syncthreads();
    if (g == 0) {
        const int tgt = rcom[c];
        float v = __ldg(&emb[(size_t)tgt * DIM + d])
                + part[0][d] + part[1][d] + part[2][d] + part[3][d] + addc;
        out[(size_t)tgt * DIM + d] = v;
    }
}

// ---------------------------------------------------------------------------
// Kernel 2: build S, flat layout — one thread per float4 of S.
// All reads are L2-hot (type rows just written by sub2). No smem, no syncs.
// ---------------------------------------------------------------------------
__global__ __launch_bounds__(256)
void build_S_kernel(const float4* __restrict__ out4,
                    const int*    __restrict__ lcom,
                    int n_typ)
{
    const int i = blockIdx.x * blockDim.x + threadIdx.x;
    if (i >= n_typ * ROWV) return;
    const int j    = i >> 5;
    const int lane = i & 31;
    int j1 = j + 1; if (j1 >= n_typ) j1 -= n_typ;
    int j2 = j + 2; if (j2 >= n_typ) j2 -= n_typ;
    int j3 = j + 3; if (j3 >= n_typ) j3 -= n_typ;
    const int t0 = __ldg(&lcom[j]);
    const int t1 = __ldg(&lcom[j1]);
    const int t2 = __ldg(&lcom[j2]);
    const int t3 = __ldg(&lcom[j3]);
    float4 v0 = __ldg(&out4[(size_t)t0 * ROWV + lane]);
    float4 v1 = __ldg(&out4[(size_t)t1 * ROWV + lane]);
    float4 v2 = __ldg(&out4[(size_t)t2 * ROWV + lane]);
    float4 v3 = __ldg(&out4[(size_t)t3 * ROWV + lane]);
    float4 s;
    s.x = (v0.x + v1.x) + (v2.x + v3.x);
    s.y = (v0.y + v1.y) + (v2.y + v3.y);
    s.z = (v0.z + v1.z) + (v2.z + v3.z);
    s.w = (v0.w + v1.w) + (v2.w + v3.w);
    g_S[i] = s;
}

// ---------------------------------------------------------------------------
// Kernel 3 (sub3), deg3==4: one warp per TWO entity rows, warp-uniform
// consecutive-pattern check -> ONE L2 gather of S[e.x] per entity (fast
// path); generic 4-gather fallback for arbitrary edges. Streaming hints on
// the entity read/write protect L2 residency of S.
// ---------------------------------------------------------------------------
__global__ __launch_bounds__(256)
void sub3_kernel(const float4* __restrict__ emb4,
                 const int4*   __restrict__ edges4,
                 const int*    __restrict__ lcom,
                 const int*    __restrict__ rspec,
                 float4*       __restrict__ out4,
                 int n_ent, int n_typ, float add, float inv_sum)
{
    const int warp = threadIdx.x >> 5;
    const int lane = threadIdx.x & 31;
    const int base = (blockIdx.x * (blockDim.x >> 5) + warp) * 2;
    if (base >= n_ent) return;
    const bool has1 = (base + 1) < n_ent;

    const int4 e0 = __ldg(&edges4[base]);
    const int4 e1 = has1 ? __ldg(&edges4[base + 1]) : e0;
    const int  r0 = __ldg(&rspec[base]);
    const int  r1 = has1 ? __ldg(&rspec[base + 1]) : r0;

    float4 iv0 = __ldcs(&emb4[(size_t)r0 * ROWV + lane]);
    float4 iv1 = __ldcs(&emb4[(size_t)r1 * ROWV + lane]);

    const int d01 = e0.y - e0.x, d02 = e0.z - e0.x, d03 = e0.w - e0.x;
    const bool ok0 = (d01 == 1 || d01 == 1 - n_typ)
                  && (d02 == 2 || d02 == 2 - n_typ)
                  && (d03 == 3 || d03 == 3 - n_typ);
    const int d11 = e1.y - e1.x, d12 = e1.z - e1.x, d13 = e1.w - e1.x;
    const bool ok1 = (d11 == 1 || d11 == 1 - n_typ)
                  && (d12 == 2 || d12 == 2 - n_typ)
                  && (d13 == 3 || d13 == 3 - n_typ);

    float4 a0, a1;
    if (ok0) {
        a0 = __ldg(&g_S[(size_t)e0.x * ROWV + lane]);
    } else {
        const int t0 = __ldg(&lcom[e0.x]), t1 = __ldg(&lcom[e0.y]);
        const int t2 = __ldg(&lcom[e0.z]), t3 = __ldg(&lcom[e0.w]);
        float4 g0 = __ldg(&out4[(size_t)t0 * ROWV + lane]);
        float4 g1 = __ldg(&out4[(size_t)t1 * ROWV + lane]);
        float4 g2 = __ldg(&out4[(size_t)t2 * ROWV + lane]);
        float4 g3 = __ldg(&out4[(size_t)t3 * ROWV + lane]);
        a0.x = (g0.x + g1.x) + (g2.x + g3.x);
        a0.y = (g0.y + g1.y) + (g2.y + g3.y);
        a0.z = (g0.z + g1.z) + (g2.z + g3.z);
        a0.w = (g0.w + g1.w) + (g2.w + g3.w);
    }
    if (ok1) {
        a1 = __ldg(&g_S[(size_t)e1.x * ROWV + lane]);
    } else {
        const int t0 = __ldg(&lcom[e1.x]), t1 = __ldg(&lcom[e1.y]);
        const int t2 = __ldg(&lcom[e1.z]), t3 = __ldg(&lcom[e1.w]);
        float4 g0 = __ldg(&out4[(size_t)t0 * ROWV + lane]);
        float4 g1 = __ldg(&out4[(size_t)t1 * ROWV + lane]);
        float4 g2 = __ldg(&out4[(size_t)t2 * ROWV + lane]);
        float4 g3 = __ldg(&out4[(size_t)t3 * ROWV + lane]);
        a1.x = (g0.x + g1.x) + (g2.x + g3.x);
        a1.y = (g0.y + g1.y) + (g2.y + g3.y);
        a1.z = (g0.z + g1.z) + (g2.z + g3.z);
        a1.w = (g0.w + g1.w) + (g2.w + g3.w);
    }

    float4 w0;
    w0.x = iv0.x * (1.0f - (a0.x + add) * inv_sum);
    w0.y = iv0.y * (1.0f - (a0.y + add) * inv_sum);
    w0.z = iv0.z * (1.0f - (a0.z + add) * inv_sum);
    w0.w = iv0.w * (1.0f - (a0.w + add) * inv_sum);
    __stcs(&out4[(size_t)r0 * ROWV + lane], w0);

    if (has1) {
        float4 w1;
        w1.x = iv1.x * (1.0f - (a1.x + add) * inv_sum);
        w1.y = iv1.y * (1.0f - (a1.y + add) * inv_sum);
        w1.z = iv1.z * (1.0f - (a1.z + add) * inv_sum);
        w1.w = iv1.w * (1.0f - (a1.w + add) * inv_sum);
        __stcs(&out4[(size_t)r1 * ROWV + lane], w1);
    }
}

// ---------------------------------------------------------------------------
// Generic sub3 fallback (deg3 != 4 or n_typ > NTYP_MAX).
// ---------------------------------------------------------------------------
__global__ __launch_bounds__(256)
void sub3_kernel_gen(const float* __restrict__ emb,
                     const int*   __restrict__ s3row,
                     const int*   __restrict__ lcom,
                     const int*   __restrict__ rspec,
                     float*       __restrict__ out,
                     int n_ent, float n_typ_f, int deg3)
{
    const int warp = threadIdx.x >> 5;
    const int lane = threadIdx.x & 31;
    const int n = blockIdx.x * (blockDim.x >> 5) + warp;
    if (n >= n_ent) return;

    const float4* __restrict__ out4 = (const float4*)out;
    const int* __restrict__ e = s3row + (size_t)n * deg3;

    float4 acc = make_float4(0.f, 0.f, 0.f, 0.f);
    for (int j = 0; j < deg3; ++j) {
        int t = __ldg(&lcom[__ldg(&e[j])]);
        float4 v = __ldg(&out4[(size_t)t * ROWV + lane]);
        acc.x += v.x; acc.y += v.y; acc.z += v.z; acc.w += v.w;
    }
    const float add     = n_typ_f - (float)deg3;
    const float inv_sum = 1.0f / (1.0f + (float)deg3);
    const int   tgt     = rspec[n];
    float4 iv = __ldcs(&((const float4*)emb)[(size_t)tgt * ROWV + lane]);
    float4 r;
    r.x = iv.x * (1.0f - (acc.x + add) * inv_sum);
    r.y = iv.y * (1.0f - (acc.y + add) * inv_sum);
    r.z = iv.z * (1.0f - (acc.z + add) * inv_sum);
    r.w = iv.w * (1.0f - (acc.w + add) * inv_sum);
    __stcs(&((float4*)out)[(size_t)tgt * ROWV + lane], r);
}

// ---------------------------------------------------------------------------
// Launch. Inputs (metadata order):
//  0 all_node_embedding f32 | 1 sub2_row | 2 sub2_col | 3 sub3_row | 4 sub3_col
//  5 left_specific | 6 right_common | 7 left_common | 8 right_specific
// ---------------------------------------------------------------------------
extern "C" void kernel_launch(void* const* d_in, const int* in_sizes, int n_in,
                              void* d_out, int out_size)
{
    const float* emb   = (const float*)d_in[0];
    const int*   s2row = (const int*)  d_in[1];
    const int*   s3row = (const int*)  d_in[3];
    const int*   lspec = (const int*)  d_in[5];
    const int*   rcom  = (const int*)  d_in[6];
    const int*   lcom  = (const int*)  d_in[7];
    const int*   rspec = (const int*)  d_in[8];
    float*       out   = (float*)d_out;

    const int n_ent = in_sizes[5];
    const int n_typ = in_sizes[6];
    const int deg2  = in_sizes[1] / n_typ;
    const int deg3  = in_sizes[3] / in_sizes[8];

    // ---- sub2: update type rows of out ----
    if (deg2 == 64) {
        sub2_kernel_d64<<<n_typ, 256>>>((const float4*)emb, (const int4*)s2row,
                                        lspec, rcom, (float4*)out,
                                        (float)n_ent - (float)deg2);
    } else {
        sub2_kernel_gen<<<n_typ, 512>>>(emb, s2row, lspec, rcom, out,
                                        (float)n_ent - (float)deg2, deg2);
    }

    if (deg3 == 4 && n_typ <= NTYP_MAX) {
        // ---- build group-sum table S (flat, no syncs) ----
        const int s_threads = 256;
        const int s_blocks  = (n_typ * ROWV + s_threads - 1) / s_threads;
        build_S_kernel<<<s_blocks, s_threads>>>((const float4*)out, lcom, n_typ);

        // ---- sub3 streaming update ----
        const int warps_per_block = 8;
        const int ents_per_block  = warps_per_block * 2;
        const int blocks = (n_ent + ents_per_block - 1) / ents_per_block;
        sub3_kernel<<<blocks, warps_per_block * 32>>>(
            (const float4*)emb, (const int4*)s3row, lcom, rspec,
            (float4*)out, n_ent, n_typ,
            (float)n_typ - 4.0f, 1.0f / 5.0f);
    } else {
        const int warps_per_block = 8;
        const int blocks = (n_ent + warps_per_block - 1) / warps_per_block;
        sub3_kernel_gen<<<blocks, warps_per_block * 32>>>(
            emb, s3row, lcom, rspec, out, n_ent, (float)n_typ, deg3);
    }
}

// round 10
// speedup vs baseline: 1.7447x; 1.0007x over previous
#include <cuda_runtime.h>
#include <cuda_bf16.h>

#define DIM   128
#define ROWV  32              // float4 per row
#define NTYP_MAX 4096
#define FUSED_GRID 592        // 4 CTAs/SM * 148 SMs -> all resident (barrier-safe)

// Precomputed group-sum table: S[j] = sum_{k=0..3} out[lcom[(j+k)%n_typ]]
__device__ float4 g_S[NTYP_MAX * ROWV];

// Monotonic barrier counter — NEVER reset, so it is graph-replay safe:
// each barrier waits for the next multiple of gridDim.x.
__device__ unsigned g_bar;

// ---------------------------------------------------------------------------
// Fused kernel: phase 1 = sub2 (grid-stride over type nodes),
// grid barrier, phase 2 = build_S. One launch instead of two.
// ---------------------------------------------------------------------------
__global__ __launch_bounds__(256, 4)
void sub2_buildS_fused(const float4* __restrict__ emb4,
                       const int4*   __restrict__ s2row4,  // s2row as int4
                       const int*    __restrict__ lspec,
                       const int*    __restrict__ rcom,
                       const int*    __restrict__ lcom,
                       float4*       __restrict__ out4,
                       float addc, int n_typ)
{
    __shared__ float4 part[8][ROWV];

    const int lane = threadIdx.x & 31;   // float4 lane within row
    const int g    = threadIdx.x >> 5;   // 0..7 edge group (8 edges each)

    // ---- phase 1: sub2, ~1.7 type nodes per CTA (pipelined by the scheduler)
    for (int c = blockIdx.x; c < n_typ; c += gridDim.x) {
        const int4 ea = __ldg(&s2row4[c * 16 + g * 2]);
        const int4 eb = __ldg(&s2row4[c * 16 + g * 2 + 1]);

        const int s0 = __ldg(&lspec[ea.x]);
        const int s1 = __ldg(&lspec[ea.y]);
        const int s2 = __ldg(&lspec[ea.z]);
        const int s3 = __ldg(&lspec[ea.w]);
        const int s4 = __ldg(&lspec[eb.x]);
        const int s5 = __ldg(&lspec[eb.y]);
        const int s6 = __ldg(&lspec[eb.z]);
        const int s7 = __ldg(&lspec[eb.w]);

        float4 v0 = __ldcs(&emb4[(size_t)s0 * ROWV + lane]);
        float4 v1 = __ldcs(&emb4[(size_t)s1 * ROWV + lane]);
        float4 v2 = __ldcs(&emb4[(size_t)s2 * ROWV + lane]);
        float4 v3 = __ldcs(&emb4[(size_t)s3 * ROWV + lane]);
        float4 v4 = __ldcs(&emb4[(size_t)s4 * ROWV + lane]);
        float4 v5 = __ldcs(&emb4[(size_t)s5 * ROWV + lane]);
        float4 v6 = __ldcs(&emb4[(size_t)s6 * ROWV + lane]);
        float4 v7 = __ldcs(&emb4[(size_t)s7 * ROWV + lane]);

        float4 a;
        a.x = ((v0.x + v1.x) + (v2.x + v3.x)) + ((v4.x + v5.x) + (v6.x + v7.x));
        a.y = ((v0.y + v1.y) + (v2.y + v3.y)) + ((v4.y + v5.y) + (v6.y + v7.y));
        a.z = ((v0.z + v1.z) + (v2.z + v3.z)) + ((v4.z + v5.z) + (v6.z + v7.z));
        a.w = ((v0.w + v1.w) + (v2.w + v3.w)) + ((v4.w + v5.w) + (v6.w + v7.w));
        part[g][lane] = a;
        __syncthreads();

        if (g == 0) {
            const int tgt = __ldg(&rcom[c]);
            float4 p0 = part[0][lane], p1 = part[1][lane];
            float4 p2 = part[2][lane], p3 = part[3][lane];
            float4 p4 = part[4][lane], p5 = part[5][lane];
            float4 p6 = part[6][lane], p7 = part[7][lane];
            float4 base = __ldg(&emb4[(size_t)tgt * ROWV + lane]);
            float4 r;
            r.x = base.x + ((p0.x + p1.x) + (p2.x + p3.x))
                         + ((p4.x + p5.x) + (p6.x + p7.x)) + addc;
            r.y = base.y + ((p0.y + p1.y) + (p2.y + p3.y))
                         + ((p4.y + p5.y) + (p6.y + p7.y)) + addc;
            r.z = base.z + ((p0.z + p1.z) + (p2.z + p3.z))
                         + ((p4.z + p5.z) + (p6.z + p7.z)) + addc;
            r.w = base.w + ((p0.w + p1.w) + (p2.w + p3.w))
                         + ((p4.w + p5.w) + (p6.w + p7.w)) + addc;
            out4[(size_t)tgt * ROWV + lane] = r;
        }
        __syncthreads();   // smem reuse guard for next node
    }

    // ---- grid barrier (all 592 CTAs resident by __launch_bounds__(256,4)) ----
    __syncthreads();
    if (threadIdx.x == 0) {
        __threadfence();                                   // release phase-1 writes
        unsigned t = atomicAdd(&g_bar, 1u) + 1u;
        unsigned target = ((t + gridDim.x - 1u) / gridDim.x) * gridDim.x;
        while (*(volatile unsigned*)&g_bar < target) { }
        __threadfence();                                   // acquire
    }
    __syncthreads();

    // ---- phase 2: build S. NOTE: reads of out4 MUST bypass the non-coherent
    // path (__ldcg, L2) because out4 was written earlier in this same launch.
    const int total  = n_typ * ROWV;
    const int stride = gridDim.x * blockDim.x;
    for (int i = blockIdx.x * blockDim.x + threadIdx.x; i < total; i += stride) {
        const int j  = i >> 5;
        const int ln = i & 31;
        int j1 = j + 1; if (j1 >= n_typ) j1 -= n_typ;
        int j2 = j + 2; if (j2 >= n_typ) j2 -= n_typ;
        int j3 = j + 3; if (j3 >= n_typ) j3 -= n_typ;
        const int t0 = __ldg(&lcom[j]);
        const int t1 = __ldg(&lcom[j1]);
        const int t2 = __ldg(&lcom[j2]);
        const int t3 = __ldg(&lcom[j3]);
        float4 v0 = __ldcg(&out4[(size_t)t0 * ROWV + ln]);
        float4 v1 = __ldcg(&out4[(size_t)t1 * ROWV + ln]);
        float4 v2 = __ldcg(&out4[(size_t)t2 * ROWV + ln]);
        float4 v3 = __ldcg(&out4[(size_t)t3 * ROWV + ln]);
        float4 s;
        s.x = (v0.x + v1.x) + (v2.x + v3.x);
        s.y = (v0.y + v1.y) + (v2.y + v3.y);
        s.z = (v0.z + v1.z) + (v2.z + v3.z);
        s.w = (v0.w + v1.w) + (v2.w + v3.w);
        g_S[i] = s;
    }
}

// ---------------------------------------------------------------------------
// Fallback kernels (generic shapes) — unchanged from R9.
// ---------------------------------------------------------------------------
__global__ __launch_bounds__(512)
void sub2_kernel_gen(const float* __restrict__ emb,
                     const int*   __restrict__ s2row,
                     const int*   __restrict__ lspec,
                     const int*   __restrict__ rcom,
                     float*       __restrict__ out,
                     float addc, int deg2)
{
    __shared__ float part[4][DIM];
    const int c = blockIdx.x;
    const int d = threadIdx.x & (DIM - 1);
    const int g = threadIdx.x >> 7;
    const int* __restrict__ e = s2row + (size_t)c * deg2;
    const int chunk = deg2 >> 2;
    const int j0 = g * chunk;
    const int j1 = (g == 3) ? deg2 : j0 + chunk;
    float acc = 0.0f;
    #pragma unroll 8
    for (int j = j0; j < j1; ++j) {
        int src = __ldg(&lspec[__ldg(&e[j])]);
        acc += __ldcs(&emb[(size_t)src * DIM + d]);
    }
    part[g][d] = acc;
    __syncthreads();
    if (g == 0) {
        const int tgt = rcom[c];
        float v = __ldg(&emb[(size_t)tgt * DIM + d])
                + part[0][d] + part[1][d] + part[2][d] + part[3][d] + addc;
        out[(size_t)tgt * DIM + d] = v;
    }
}

__global__ __launch_bounds__(256)
void build_S_kernel(const float4* __restrict__ out4,
                    const int*    __restrict__ lcom,
                    int n_typ)
{
    const int i = blockIdx.x * blockDim.x + threadIdx.x;
    if (i >= n_typ * ROWV) return;
    const int j    = i >> 5;
    const int lane = i & 31;
    int j1 = j + 1; if (j1 >= n_typ) j1 -= n_typ;
    int j2 = j + 2; if (j2 >= n_typ) j2 -= n_typ;
    int j3 = j + 3; if (j3 >= n_typ) j3 -= n_typ;
    const int t0 = __ldg(&lcom[j]);
    const int t1 = __ldg(&lcom[j1]);
    const int t2 = __ldg(&lcom[j2]);
    const int t3 = __ldg(&lcom[j3]);
    float4 v0 = __ldg(&out4[(size_t)t0 * ROWV + lane]);
    float4 v1 = __ldg(&out4[(size_t)t1 * ROWV + lane]);
    float4 v2 = __ldg(&out4[(size_t)t2 * ROWV + lane]);
    float4 v3 = __ldg(&out4[(size_t)t3 * ROWV + lane]);
    float4 s;
    s.x = (v0.x + v1.x) + (v2.x + v3.x);
    s.y = (v0.y + v1.y) + (v2.y + v3.y);
    s.z = (v0.z + v1.z) + (v2.z + v3.z);
    s.w = (v0.w + v1.w) + (v2.w + v3.w);
    g_S[i] = s;
}

// ---------------------------------------------------------------------------
// sub3 (deg3==4): one warp per TWO entity rows, warp-uniform consecutive
// pattern check -> ONE L2 gather of S per entity; 4-gather fallback.
// ---------------------------------------------------------------------------
__global__ __launch_bounds__(256)
void sub3_kernel(const float4* __restrict__ emb4,
                 const int4*   __restrict__ edges4,
                 const int*    __restrict__ lcom,
                 const int*    __restrict__ rspec,
                 float4*       __restrict__ out4,
                 int n_ent, int n_typ, float add, float inv_sum)
{
    const int warp = threadIdx.x >> 5;
    const int lane = threadIdx.x & 31;
    const int base = (blockIdx.x * (blockDim.x >> 5) + warp) * 2;
    if (base >= n_ent) return;
    const bool has1 = (base + 1) < n_ent;

    const int4 e0 = __ldg(&edges4[base]);
    const int4 e1 = has1 ? __ldg(&edges4[base + 1]) : e0;
    const int  r0 = __ldg(&rspec[base]);
    const int  r1 = has1 ? __ldg(&rspec[base + 1]) : r0;

    float4 iv0 = __ldcs(&emb4[(size_t)r0 * ROWV + lane]);
    float4 iv1 = __ldcs(&emb4[(size_t)r1 * ROWV + lane]);

    const int d01 = e0.y - e0.x, d02 = e0.z - e0.x, d03 = e0.w - e0.x;
    const bool ok0 = (d01 == 1 || d01 == 1 - n_typ)
                  && (d02 == 2 || d02 == 2 - n_typ)
                  && (d03 == 3 || d03 == 3 - n_typ);
    const int d11 = e1.y - e1.x, d12 = e1.z - e1.x, d13 = e1.w - e1.x;
    const bool ok1 = (d11 == 1 || d11 == 1 - n_typ)
                  && (d12 == 2 || d12 == 2 - n_typ)
                  && (d13 == 3 || d13 == 3 - n_typ);

    float4 a0, a1;
    if (ok0) {
        a0 = __ldg(&g_S[(size_t)e0.x * ROWV + lane]);
    } else {
        const int t0 = __ldg(&lcom[e0.x]), t1 = __ldg(&lcom[e0.y]);
        const int t2 = __ldg(&lcom[e0.z]), t3 = __ldg(&lcom[e0.w]);
        float4 g0 = __ldg(&out4[(size_t)t0 * ROWV + lane]);
        float4 g1 = __ldg(&out4[(size_t)t1 * ROWV + lane]);
        float4 g2 = __ldg(&out4[(size_t)t2 * ROWV + lane]);
        float4 g3 = __ldg(&out4[(size_t)t3 * ROWV + lane]);
        a0.x = (g0.x + g1.x) + (g2.x + g3.x);
        a0.y = (g0.y + g1.y) + (g2.y + g3.y);
        a0.z = (g0.z + g1.z) + (g2.z + g3.z);
        a0.w = (g0.w + g1.w) + (g2.w + g3.w);
    }
    if (ok1) {
        a1 = __ldg(&g_S[(size_t)e1.x * ROWV + lane]);
    } else {
        const int t0 = __ldg(&lcom[e1.x]), t1 = __ldg(&lcom[e1.y]);
        const int t2 = __ldg(&lcom[e1.z]), t3 = __ldg(&lcom[e1.w]);
        float4 g0 = __ldg(&out4[(size_t)t0 * ROWV + lane]);
        float4 g1 = __ldg(&out4[(size_t)t1 * ROWV + lane]);
        float4 g2 = __ldg(&out4[(size_t)t2 * ROWV + lane]);
        float4 g3 = __ldg(&out4[(size_t)t3 * ROWV + lane]);
        a1.x = (g0.x + g1.x) + (g2.x + g3.x);
        a1.y = (g0.y + g1.y) + (g2.y + g3.y);
        a1.z = (g0.z + g1.z) + (g2.z + g3.z);
        a1.w = (g0.w + g1.w) + (g2.w + g3.w);
    }

    float4 w0;
    w0.x = iv0.x * (1.0f - (a0.x + add) * inv_sum);
    w0.y = iv0.y * (1.0f - (a0.y + add) * inv_sum);
    w0.z = iv0.z * (1.0f - (a0.z + add) * inv_sum);
    w0.w = iv0.w * (1.0f - (a0.w + add) * inv_sum);
    __stcs(&out4[(size_t)r0 * ROWV + lane], w0);

    if (has1) {
        float4 w1;
        w1.x = iv1.x * (1.0f - (a1.x + add) * inv_sum);
        w1.y = iv1.y * (1.0f - (a1.y + add) * inv_sum);
        w1.z = iv1.z * (1.0f - (a1.z + add) * inv_sum);
        w1.w = iv1.w * (1.0f - (a1.w + add) * inv_sum);
        __stcs(&out4[(size_t)r1 * ROWV + lane], w1);
    }
}

__global__ __launch_bounds__(256)
void sub3_kernel_gen(const float* __restrict__ emb,
                     const int*   __restrict__ s3row,
                     const int*   __restrict__ lcom,
                     const int*   __restrict__ rspec,
                     float*       __restrict__ out,
                     int n_ent, float n_typ_f, int deg3)
{
    const int warp = threadIdx.x >> 5;
    const int lane = threadIdx.x & 31;
    const int n = blockIdx.x * (blockDim.x >> 5) + warp;
    if (n >= n_ent) return;

    const float4* __restrict__ out4 = (const float4*)out;
    const int* __restrict__ e = s3row + (size_t)n * deg3;

    float4 acc = make_float4(0.f, 0.f, 0.f, 0.f);
    for (int j = 0; j < deg3; ++j) {
        int t = __ldg(&lcom[__ldg(&e[j])]);
        float4 v = __ldg(&out4[(size_t)t * ROWV + lane]);
        acc.x += v.x; acc.y += v.y; acc.z += v.z; acc.w += v.w;
    }
    const float add     = n_typ_f - (float)deg3;
    const float inv_sum = 1.0f / (1.0f + (float)deg3);
    const int   tgt     = rspec[n];
    float4 iv = __ldcs(&((const float4*)emb)[(size_t)tgt * ROWV + lane]);
    float4 r;
    r.x = iv.x * (1.0f - (acc.x + add) * inv_sum);
    r.y = iv.y * (1.0f - (acc.y + add) * inv_sum);
    r.z = iv.z * (1.0f - (acc.z + add) * inv_sum);
    r.w = iv.w * (1.0f - (acc.w + add) * inv_sum);
    __stcs(&((float4*)out)[(size_t)tgt * ROWV + lane], r);
}

// ---------------------------------------------------------------------------
// Launch. Inputs (metadata order):
//  0 all_node_embedding f32 | 1 sub2_row | 2 sub2_col | 3 sub3_row | 4 sub3_col
//  5 left_specific | 6 right_common | 7 left_common | 8 right_specific
// ---------------------------------------------------------------------------
extern "C" void kernel_launch(void* const* d_in, const int* in_sizes, int n_in,
                              void* d_out, int out_size)
{
    const float* emb   = (const float*)d_in[0];
    const int*   s2row = (const int*)  d_in[1];
    const int*   s3row = (const int*)  d_in[3];
    const int*   lspec = (const int*)  d_in[5];
    const int*   rcom  = (const int*)  d_in[6];
    const int*   lcom  = (const int*)  d_in[7];
    const int*   rspec = (const int*)  d_in[8];
    float*       out   = (float*)d_out;

    const int n_ent = in_sizes[5];
    const int n_typ = in_sizes[6];
    const int deg2  = in_sizes[1] / n_typ;
    const int deg3  = in_sizes[3] / in_sizes[8];

    if (deg2 == 64 && deg3 == 4 && n_typ <= NTYP_MAX) {
        // ---- fused sub2 + barrier + build_S (one launch) ----
        sub2_buildS_fused<<<FUSED_GRID, 256>>>(
            (const float4*)emb, (const int4*)s2row, lspec, rcom, lcom,
            (float4*)out, (float)n_ent - (float)deg2, n_typ);

        // ---- sub3 streaming update ----
        const int warps_per_block = 8;
        const int ents_per_block  = warps_per_block * 2;
        const int blocks = (n_ent + ents_per_block - 1) / ents_per_block;
        sub3_kernel<<<blocks, warps_per_block * 32>>>(
            (const float4*)emb, (const int4*)s3row, lcom, rspec,
            (float4*)out, n_ent, n_typ,
            (float)n_typ - 4.0f, 1.0f / 5.0f);
    } else {
        // ---- generic fallback path ----
        sub2_kernel_gen<<<n_typ, 512>>>(emb, s2row, lspec, rcom, out,
                                        (float)n_ent - (float)deg2, deg2);
        if (deg3 == 4 && n_typ <= NTYP_MAX) {
            const int s_threads = 256;
            const int s_blocks  = (n_typ * ROWV + s_threads - 1) / s_threads;
            build_S_kernel<<<s_blocks, s_threads>>>((const float4*)out, lcom, n_typ);
            const int warps_per_block = 8;
            const int ents_per_block  = warps_per_block * 2;
            const int blocks = (n_ent + ents_per_block - 1) / ents_per_block;
            sub3_kernel<<<blocks, warps_per_block * 32>>>(
                (const float4*)emb, (const int4*)s3row, lcom, rspec,
                (float4*)out, n_ent, n_typ,
                (float)n_typ - 4.0f, 1.0f / 5.0f);
        } else {
            const int warps_per_block = 8;
            const int blocks = (n_ent + warps_per_block - 1) / warps_per_block;
            sub3_kernel_gen<<<blocks, warps_per_block * 32>>>(
                emb, s3row, lcom, rspec, out, n_ent, (float)n_typ, deg3);
        }
    }
}